// round 10
// baseline (speedup 1.0000x reference)
#include <cuda_runtime.h>
#include <cstdint>

#define TT 2048
#define BB 512
#define HH 32
#define CPB 2            // batch elements per CTA
#define NCTA (BB / CPB)  // 256

// ---------- packed f32x2 helpers (Blackwell FFMA2/FADD2 via inline PTX) ----------
__device__ __forceinline__ uint64_t pack2(float lo, float hi) {
    uint64_t r;
    asm("mov.b64 %0, {%1, %2};" : "=l"(r) : "f"(lo), "f"(hi));
    return r;
}
__device__ __forceinline__ void unpack2(uint64_t v, float& lo, float& hi) {
    asm("mov.b64 {%0, %1}, %2;" : "=f"(lo), "=f"(hi) : "l"(v));
}
__device__ __forceinline__ uint64_t fma2(uint64_t a, uint64_t b, uint64_t c) {
    uint64_t d;
    asm("fma.rn.f32x2 %0, %1, %2, %3;" : "=l"(d) : "l"(a), "l"(b), "l"(c));
    return d;
}
__device__ __forceinline__ uint64_t add2(uint64_t a, uint64_t b) {
    uint64_t d;
    asm("add.rn.f32x2 %0, %1, %2;" : "=l"(d) : "l"(a), "l"(b));
    return d;
}

// Unified activation: act(x) = fma(rcp(1 + ex2(k*x)), m, c)
//   sigmoid: k=-log2(e),  m= 1, c=0      tanh: k=2log2(e), m=-2, c=1
__device__ __forceinline__ float fact(float x, float k, float m, float c) {
    float r;
    asm("{\n\t"
        ".reg .f32 t;\n\t"
        "mul.f32 t, %1, %2;\n\t"
        "ex2.approx.f32 t, t;\n\t"
        "add.f32 t, t, 0f3F800000;\n\t"
        "rcp.approx.f32 t, t;\n\t"
        "fma.rn.f32 %0, t, %3, %4;\n\t"
        "}" : "=f"(r) : "f"(x), "f"(k), "f"(m), "f"(c));
    return r;
}
__device__ __forceinline__ float ftanh(float x) {
    float r;
    asm("{\n\t"
        ".reg .f32 t;\n\t"
        "mul.f32 t, %1, 0f4038AA3B;\n\t"   // 2*log2(e)
        "ex2.approx.f32 t, t;\n\t"
        "add.f32 t, t, 0f3F800000;\n\t"
        "rcp.approx.f32 t, t;\n\t"
        "fma.rn.f32 %0, t, 0fC0000000, 0f3F800000;\n\t"
        "}" : "=f"(r) : "f"(x));
    return r;
}

// 256 CTAs, 2 batch elements each, 128 threads, occ 2 (reg cap 256 -> no
// spill risk; ~132 live regs). Weights shared across the pair: 96 regs once,
// 2x the independent FMA chains per warp for latency hiding on 1-CTA SMs.
// Quad-gate layout: lane = unit_local*4 + gate; g==0 lane owns cell state
// (3-shfl gather; other lanes run identical dead-result instructions).
// FUSED-PHASE SCHEDULE (1 barrier/step serves BOTH elements): phase t reads
// hcat[e][p] = [h0(t) | h1(t-1)], computes L1(t) + L0(t+1) for both elements,
// writes hcat[e][p^1] = [h0(t+1) | h1(t)], then one BAR.
__global__ void __launch_bounds__(128, 2) lstm2_kernel(
    const float* __restrict__ x,
    const float* __restrict__ W_ih0, const float* __restrict__ W_hh0,
    const float* __restrict__ b_ih0, const float* __restrict__ b_hh0,
    const float* __restrict__ W_ih1, const float* __restrict__ W_hh1,
    const float* __restrict__ b_ih1, const float* __restrict__ b_hh1,
    const float* __restrict__ W_d,   const float* __restrict__ b_d,
    float* __restrict__ out)
{
    __shared__ __align__(16) float hcat[CPB][2][64]; // [elem][buf][h0|h1]
    __shared__ float part[2][CPB][4];                // [buf][elem][warp]

    const int tid  = threadIdx.x;
    const int lane = tid & 31;
    const int w    = tid >> 5;
    const int g    = lane & 3;            // 0=i 1=f 2=g 3=o
    const int u    = w * 8 + (lane >> 2); // hidden unit 0..31
    const int b0   = blockIdx.x * CPB;    // even -> float2-aligned
    const int row  = g * HH + u;
    const int qb   = lane & ~3;

    // ---- weight rows -> registers as (even_k, odd_k) f32x2 pairs ----
    uint64_t wh0[16], wi1[16], wh1[16];
    {
        const uint64_t* r0 = (const uint64_t*)(W_hh0 + row * HH);
        const uint64_t* r1 = (const uint64_t*)(W_ih1 + row * HH);
        const uint64_t* r2 = (const uint64_t*)(W_hh1 + row * HH);
#pragma unroll
        for (int k = 0; k < 16; k++) { wh0[k] = r0[k]; wi1[k] = r1[k]; wh1[k] = r2[k]; }
    }
    const float wx0       = W_ih0[row];                // IN = 1
    const float bias0     = b_ih0[row] + b_hh0[row];
    const uint64_t bias1p = pack2(b_ih1[row] + b_hh1[row], 0.f);
    const float wd        = W_d[u];
    const float bd        = b_d[0];

    const float ak = (g == 2) ?  2.885390082f : -1.442695041f;
    const float am = (g == 2) ? -2.0f         :  1.0f;
    const float ac = (g == 2) ?  1.0f         :  0.0f;

    float c0[CPB] = {0.f, 0.f}, c1[CPB] = {0.f, 0.f};
    ((float*)hcat)[tid]       = 0.f;   // zero all 256 floats
    ((float*)hcat)[tid + 128] = 0.f;
    __syncthreads();

    const float* const xp = x + b0;   // fixed base; prefetch via int offset

    // ---- prologue: L0(0) from h0(-1)=0 for both elements ----
    float2 xv = *(const float2*)xp;   // x(0) for b0, b0+1
    {
#pragma unroll
        for (int e = 0; e < CPB; e++) {
            const float xe = (e == 0) ? xv.x : xv.y;
            const float act0 = fact(fmaf(xe, wx0, bias0), ak, am, ac);
            const float gg = __shfl_sync(0xffffffffu, act0, qb + 2);
            const float go = __shfl_sync(0xffffffffu, act0, qb + 3);
            c0[e] = act0 * gg;               // f*c_prev = 0
            const float h0v = go * ftanh(c0[e]);
            if (g == 0) hcat[e][0][u] = h0v; // h1(-1)=0 already zeroed
        }
    }
    int off = BB;
    xv = __ldg((const float2*)(xp + off));   // prefetch x(1)
    __syncthreads();

    for (int t = 0; t < TT; t++) {
        const int p  = t & 1;
        const int np = p ^ 1;
        const float2 xc = xv;                // x(t+1), clamped at tail
        off += (t + 2 < TT) ? BB : 0;
        xv = __ldg((const float2*)(xp + off));

        // ==== fused phase: L1(t) + L0(t+1) for BOTH elements (6 chains) ====
        uint64_t a1A[CPB], a1B[CPB], a0A[CPB];
        a1A[0] = bias1p;  a1A[1] = bias1p;
        a1B[0] = 0;       a1B[1] = 0;
        a0A[0] = pack2(fmaf(xc.x, wx0, bias0), 0.f);
        a0A[1] = pack2(fmaf(xc.y, wx0, bias0), 0.f);
        {
            const ulonglong2* hA = (const ulonglong2*)hcat[0][p];
            const ulonglong2* hB = (const ulonglong2*)hcat[1][p];
#pragma unroll
            for (int k = 0; k < 8; k++) {
                const ulonglong2 ha0 = hA[k];      // e0 h0(t)   (LDS.128 bcast)
                const ulonglong2 hb0 = hA[k + 8];  // e0 h1(t-1)
                const ulonglong2 ha1 = hB[k];      // e1 h0(t)
                const ulonglong2 hb1 = hB[k + 8];  // e1 h1(t-1)
                a1A[0] = fma2(wi1[2 * k],     ha0.x, a1A[0]);
                a1A[0] = fma2(wi1[2 * k + 1], ha0.y, a1A[0]);
                a1B[0] = fma2(wh1[2 * k],     hb0.x, a1B[0]);
                a1B[0] = fma2(wh1[2 * k + 1], hb0.y, a1B[0]);
                a0A[0] = fma2(wh0[2 * k],     ha0.x, a0A[0]);
                a0A[0] = fma2(wh0[2 * k + 1], ha0.y, a0A[0]);
                a1A[1] = fma2(wi1[2 * k],     ha1.x, a1A[1]);
                a1A[1] = fma2(wi1[2 * k + 1], ha1.y, a1A[1]);
                a1B[1] = fma2(wh1[2 * k],     hb1.x, a1B[1]);
                a1B[1] = fma2(wh1[2 * k + 1], hb1.y, a1B[1]);
                a0A[1] = fma2(wh0[2 * k],     ha1.x, a0A[1]);
                a0A[1] = fma2(wh0[2 * k + 1], ha1.y, a0A[1]);
            }
        }

        float pr[CPB];
#pragma unroll
        for (int e = 0; e < CPB; e++) {
            float lo, hi;
            unpack2(add2(a1A[e], a1B[e]), lo, hi);
            const float act1 = fact(lo + hi, ak, am, ac);
            unpack2(a0A[e], lo, hi);
            const float act0 = fact(lo + hi, ak, am, ac);

            // quad gathers (g0 lane owns cell; others run dead copies)
            const float gf1 = __shfl_sync(0xffffffffu, act1, qb + 1);
            const float gg1 = __shfl_sync(0xffffffffu, act1, qb + 2);
            const float go1 = __shfl_sync(0xffffffffu, act1, qb + 3);
            c1[e] = fmaf(gf1, c1[e], act1 * gg1);  // act1 == i-gate in g0 lane
            const float h1v = go1 * ftanh(c1[e]);

            const float gf0 = __shfl_sync(0xffffffffu, act0, qb + 1);
            const float gg0 = __shfl_sync(0xffffffffu, act0, qb + 2);
            const float go0 = __shfl_sync(0xffffffffu, act0, qb + 3);
            c0[e] = fmaf(gf0, c0[e], act0 * gg0);
            const float h0v = go0 * ftanh(c0[e]);

            if (g == 0) {
                hcat[e][np][u]      = h0v;   // h0(t+1)
                hcat[e][np][32 + u] = h1v;   // h1(t)
            }

            // dense head: nonzero partials only at lanes 0 mod 4
            float q = (g == 0) ? h1v * wd : 0.f;
            q += __shfl_xor_sync(0xffffffffu, q, 4);
            q += __shfl_xor_sync(0xffffffffu, q, 8);
            q += __shfl_xor_sync(0xffffffffu, q, 16);
            pr[e] = q;
        }
        if (lane == 0) { part[p][0][w] = pr[0]; part[p][1][w] = pr[1]; }

        __syncthreads();                     // single barrier, both elements

        if (tid == 0) {
            float2 o;
            o.x = (part[p][0][0] + part[p][0][1]) + (part[p][0][2] + part[p][0][3]) + bd;
            o.y = (part[p][1][0] + part[p][1][1]) + (part[p][1][2] + part[p][1][3]) + bd;
            *(float2*)(out + b0 + t * BB) = o;   // STG.64, 8B-aligned
        }
        // part[p] is next written in phase t+2, behind BAR(t+1) -> no race
    }
}

extern "C" void kernel_launch(void* const* d_in, const int* in_sizes, int n_in,
                              void* d_out, int out_size)
{
    const float* x     = (const float*)d_in[0];
    const float* W_ih0 = (const float*)d_in[1];
    const float* W_hh0 = (const float*)d_in[2];
    const float* b_ih0 = (const float*)d_in[3];
    const float* b_hh0 = (const float*)d_in[4];
    const float* W_ih1 = (const float*)d_in[5];
    const float* W_hh1 = (const float*)d_in[6];
    const float* b_ih1 = (const float*)d_in[7];
    const float* b_hh1 = (const float*)d_in[8];
    const float* W_d   = (const float*)d_in[9];
    const float* b_d   = (const float*)d_in[10];

    lstm2_kernel<<<NCTA, 128>>>(x, W_ih0, W_hh0, b_ih0, b_hh0,
                                W_ih1, W_hh1, b_ih1, b_hh1,
                                W_d, b_d, (float*)d_out);
}